// round 1
// baseline (speedup 1.0000x reference)
#include <cuda_runtime.h>
#include <cstdint>

#define BATCH    8
#define CDIM     512
#define NPOS     2048
#define HEADS    8
#define DIM_HEAD 64
#define HIDDEN   512          /* HEADS*DIM_HEAD */
#define QKV_ROWS 1536
#define EPS_LN   1e-5f

/* ---------------- scratch (static device globals; no cudaMalloc allowed) -------- */
__device__ float g_xn [BATCH * CDIM * NPOS];        /* 32 MB  normalized x        */
__device__ float g_qkv[BATCH * QKV_ROWS * NPOS];    /* 96 MB  q,k,v               */
__device__ float g_ao [BATCH * HIDDEN * NPOS];      /* 32 MB  attention output    */

/* ---------------- packed f32x2 helpers (FFMA2 doubles fp32 throughput) --------- */
__device__ __forceinline__ unsigned long long pk2(float lo, float hi) {
    unsigned long long r;
    asm("mov.b64 %0, {%1, %2};" : "=l"(r) : "f"(lo), "f"(hi));
    return r;
}
__device__ __forceinline__ void upk2(unsigned long long v, float &lo, float &hi) {
    asm("mov.b64 {%0, %1}, %2;" : "=f"(lo), "=f"(hi) : "l"(v));
}
__device__ __forceinline__ unsigned long long ffma2(unsigned long long a,
                                                    unsigned long long b,
                                                    unsigned long long c) {
    unsigned long long d;
    asm("fma.rn.f32x2 %0, %1, %2, %3;" : "=l"(d) : "l"(a), "l"(b), "l"(c));
    return d;
}
__device__ __forceinline__ unsigned long long fmul2(unsigned long long a,
                                                    unsigned long long b) {
    unsigned long long d;
    asm("mul.rn.f32x2 %0, %1, %2;" : "=l"(d) : "l"(a), "l"(b));
    return d;
}

/* =====================================================================
 * Kernel 1: channel LayerNorm.  x[b,c,n] -> xn[b,c,n]
 * block = 256 threads = 64 n-positions x 4 c-slices (128 c each).
 * ===================================================================== */
__global__ void ln_kernel(const float* __restrict__ x,
                          const float* __restrict__ g,
                          float* __restrict__ xn) {
    __shared__ float gs[CDIM];
    __shared__ float red[2][4][64];
    int t = threadIdx.x;
    for (int c = t; c < CDIM; c += 256) gs[c] = g[c];

    int nl = t & 63;          /* local n     */
    int cs = t >> 6;          /* c slice 0..3 */
    int pos0 = blockIdx.x * 64;           /* 2048 % 64 == 0: never straddles b */
    int b  = pos0 / NPOS;
    int n0 = pos0 % NPOS;

    const float* xp = x + (long)b * CDIM * NPOS + n0 + nl;
    float s = 0.f, ss = 0.f;
    #pragma unroll 8
    for (int c = cs * 128; c < cs * 128 + 128; c++) {
        float v = xp[(long)c * NPOS];
        s += v; ss += v * v;
    }
    red[0][cs][nl] = s;  red[1][cs][nl] = ss;
    __syncthreads();
    float st  = red[0][0][nl] + red[0][1][nl] + red[0][2][nl] + red[0][3][nl];
    float sst = red[1][0][nl] + red[1][1][nl] + red[1][2][nl] + red[1][3][nl];
    float mean = st * (1.f / CDIM);
    float inv  = rsqrtf(sst * (1.f / CDIM) - mean * mean + EPS_LN);

    float* op = xn + (long)b * CDIM * NPOS + n0 + nl;
    #pragma unroll 8
    for (int c = cs * 128; c < cs * 128 + 128; c++) {
        float v = xp[(long)c * NPOS];
        op[(long)c * NPOS] = (v - mean) * inv * gs[c];
    }
}

/* =====================================================================
 * Kernel 2/4: C[b,m,n] = sum_k A[m,k]*B[b,k,n] (+bias[m])
 * A row-major [M,K] (small weight), B [K,NPOS] per batch, N=NPOS.
 * Tile: 128(M) x 64(N) x 16(K), 256 threads, per-thread 8x4 via f32x2.
 * Requires M%128==0, K%16==0.
 * ===================================================================== */
__global__ void __launch_bounds__(256)
gemm_wx(const float* __restrict__ A, const float* __restrict__ Bm,
        float* __restrict__ C, const float* __restrict__ bias,
        int M, int K) {
    __shared__ float As[16][128];
    __shared__ float Bs[16][64];
    int t  = threadIdx.x;
    int m0 = blockIdx.x * 128;
    int n0 = blockIdx.y * 64;
    int b  = blockIdx.z;
    const float* Bb = Bm + (long)b * K * NPOS;
    float*       Cb = C  + (long)b * M * NPOS;

    int tm = t >> 4;            /* 0..15 */
    int tn = t & 15;            /* 0..15 */
    int mb = tm * 8, nb = tn * 4;

    unsigned long long acc[4][4];   /* [m-pair][n] */
    #pragma unroll
    for (int i = 0; i < 4; i++)
        #pragma unroll
        for (int j = 0; j < 4; j++) acc[i][j] = 0ull;

    for (int k0 = 0; k0 < K; k0 += 16) {
        /* load A tile 128x16 (transposed into smem) */
        #pragma unroll
        for (int s = 0; s < 2; s++) {
            int lin = s * 256 + t;                 /* 0..511 float4s */
            int row = lin >> 2, q = (lin & 3) * 4;
            float4 av = *(const float4*)(A + (long)(m0 + row) * K + k0 + q);
            As[q + 0][row] = av.x; As[q + 1][row] = av.y;
            As[q + 2][row] = av.z; As[q + 3][row] = av.w;
        }
        /* load B tile 16x64 */
        {
            int row = t >> 4, q = (t & 15) * 4;
            *(float4*)&Bs[row][q] =
                *(const float4*)(Bb + (long)(k0 + row) * NPOS + n0 + q);
        }
        __syncthreads();
        #pragma unroll
        for (int kk = 0; kk < 16; kk++) {
            ulonglong2 aA = *(ulonglong2*)&As[kk][mb];
            ulonglong2 aB = *(ulonglong2*)&As[kk][mb + 4];
            unsigned long long ap[4] = {aA.x, aA.y, aB.x, aB.y};
            float4 b4 = *(float4*)&Bs[kk][nb];
            unsigned long long bp[4] = {pk2(b4.x, b4.x), pk2(b4.y, b4.y),
                                        pk2(b4.z, b4.z), pk2(b4.w, b4.w)};
            #pragma unroll
            for (int mp = 0; mp < 4; mp++)
                #pragma unroll
                for (int n = 0; n < 4; n++)
                    acc[mp][n] = ffma2(ap[mp], bp[n], acc[mp][n]);
        }
        __syncthreads();
    }

    #pragma unroll
    for (int mp = 0; mp < 4; mp++) {
        float lo[4], hi[4];
        #pragma unroll
        for (int n = 0; n < 4; n++) upk2(acc[mp][n], lo[n], hi[n]);
        int m_lo = m0 + mb + 2 * mp, m_hi = m_lo + 1;
        float b0 = bias ? bias[m_lo] : 0.f;
        float b1 = bias ? bias[m_hi] : 0.f;
        float4 vlo = make_float4(lo[0] + b0, lo[1] + b0, lo[2] + b0, lo[3] + b0);
        float4 vhi = make_float4(hi[0] + b1, hi[1] + b1, hi[2] + b1, hi[3] + b1);
        *(float4*)(Cb + (long)m_lo * NPOS + n0 + nb) = vlo;
        *(float4*)(Cb + (long)m_hi * NPOS + n0 + nb) = vhi;
    }
}

/* =====================================================================
 * Kernel 3: fused flash attention per (b,h).
 * Block: 128 query positions, loops 32 kv tiles of 64.
 * smem: Qs[64][128] Ks[64][64] Vt[64][68] Ps[128][68]  = 101376 B (dynamic)
 * Thread map: ig=t>>3 (i tile of 4), jg=t&7 (8 j's in S phase / 8 d's in PV).
 * ===================================================================== */
#define QS(d,i)  Qs[(d) * 128 + (i)]
#define KS(d,j)  Ks[(d) * 64 + (j)]
#define VT(j,d)  Vt[(j) * 68 + (d)]
#define PSM(i,j) Ps[(i) * 68 + (j)]

__global__ void __launch_bounds__(256, 2)
attn_kernel(const float* __restrict__ qkv, float* __restrict__ ao) {
    extern __shared__ float sm[];
    float* Qs = sm;                       /* 8192  */
    float* Ks = sm + 8192;                /* 4096  */
    float* Vt = sm + 12288;               /* 4352  */
    float* Ps = sm + 16640;               /* 8704  */

    int t  = threadIdx.x;
    int qt = blockIdx.x;                  /* 0..15 */
    int bh = blockIdx.y;                  /* 0..63 */
    int b  = bh >> 3, h = bh & 7;
    const float scale = 0.125f;           /* DIM_HEAD^-0.5 */

    long base = (long)b * QKV_ROWS * NPOS + (long)h * DIM_HEAD * NPOS;
    const float* qp = qkv + base;
    const float* kp = qkv + base + (long)HIDDEN * NPOS;
    const float* vp = qkv + base + 2L * HIDDEN * NPOS;
    int i0 = qt * 128;

    /* load Q tile (scaled) */
    #pragma unroll
    for (int s = 0; s < 8; s++) {
        int lin = s * 256 + t;            /* 0..2047 float4s */
        int d = lin >> 5, i = (lin & 31) << 2;
        float4 v = *(const float4*)(qp + (long)d * NPOS + i0 + i);
        v.x *= scale; v.y *= scale; v.z *= scale; v.w *= scale;
        *(float4*)&QS(d, i) = v;
    }

    int ig = t >> 3, jg = t & 7;
    int i_base = ig * 4;
    int jd_base = jg * 8;                 /* j_base in S phase, d_base in PV */

    float m_i[4], l_i[4];
    unsigned long long o2[4][4];          /* O[4 rows][8 d] as d-pairs */
    #pragma unroll
    for (int r = 0; r < 4; r++) {
        m_i[r] = -1e30f; l_i[r] = 0.f;
        #pragma unroll
        for (int c = 0; c < 4; c++) o2[r][c] = 0ull;
    }

    for (int j0 = 0; j0 < NPOS; j0 += 64) {
        /* load K tile [d][j] */
        #pragma unroll
        for (int s = 0; s < 4; s++) {
            int lin = s * 256 + t;        /* 0..1023 float4s */
            int d = lin >> 4, j = (lin & 15) << 2;
            *(float4*)&KS(d, j) = *(const float4*)(kp + (long)d * NPOS + j0 + j);
        }
        /* load V tile transposed -> Vt[j][d] */
        #pragma unroll
        for (int s = 0; s < 4; s++) {
            int lin = s * 256 + t;
            int d = lin >> 4, j = (lin & 15) << 2;
            float4 v = *(const float4*)(vp + (long)d * NPOS + j0 + j);
            VT(j + 0, d) = v.x; VT(j + 1, d) = v.y;
            VT(j + 2, d) = v.z; VT(j + 3, d) = v.w;
        }
        __syncthreads();                  /* (a) tiles ready */

        /* ---- S = Q^T K : per-thread 4(i) x 8(j), j packed in pairs ---- */
        unsigned long long s2[4][4];
        #pragma unroll
        for (int r = 0; r < 4; r++)
            #pragma unroll
            for (int c = 0; c < 4; c++) s2[r][c] = 0ull;

        #pragma unroll 8
        for (int d = 0; d < 64; d++) {
            ulonglong2 k01 = *(ulonglong2*)&KS(d, jd_base);
            ulonglong2 k23 = *(ulonglong2*)&KS(d, jd_base + 4);
            unsigned long long kpair[4] = {k01.x, k01.y, k23.x, k23.y};
            float4 q4 = *(float4*)&QS(d, i_base);
            unsigned long long qq[4] = {pk2(q4.x, q4.x), pk2(q4.y, q4.y),
                                        pk2(q4.z, q4.z), pk2(q4.w, q4.w)};
            #pragma unroll
            for (int r = 0; r < 4; r++)
                #pragma unroll
                for (int c = 0; c < 4; c++)
                    s2[r][c] = ffma2(qq[r], kpair[c], s2[r][c]);
        }

        /* ---- online softmax (row groups of 8 lanes: jg = lane&7) ---- */
        #pragma unroll
        for (int r = 0; r < 4; r++) {
            float sv[8];
            upk2(s2[r][0], sv[0], sv[1]); upk2(s2[r][1], sv[2], sv[3]);
            upk2(s2[r][2], sv[4], sv[5]); upk2(s2[r][3], sv[6], sv[7]);
            float mx = sv[0];
            #pragma unroll
            for (int c = 1; c < 8; c++) mx = fmaxf(mx, sv[c]);
            mx = fmaxf(mx, __shfl_xor_sync(0xffffffffu, mx, 1));
            mx = fmaxf(mx, __shfl_xor_sync(0xffffffffu, mx, 2));
            mx = fmaxf(mx, __shfl_xor_sync(0xffffffffu, mx, 4));
            float mnew = fmaxf(m_i[r], mx);
            float sum = 0.f;
            #pragma unroll
            for (int c = 0; c < 8; c++) {
                float p = __expf(sv[c] - mnew);
                sv[c] = p; sum += p;
            }
            sum += __shfl_xor_sync(0xffffffffu, sum, 1);
            sum += __shfl_xor_sync(0xffffffffu, sum, 2);
            sum += __shfl_xor_sync(0xffffffffu, sum, 4);
            float alpha = __expf(m_i[r] - mnew);
            l_i[r] = l_i[r] * alpha + sum;
            m_i[r] = mnew;
            unsigned long long aa = pk2(alpha, alpha);
            #pragma unroll
            for (int c = 0; c < 4; c++) o2[r][c] = fmul2(o2[r][c], aa);
            *(float4*)&PSM(i_base + r, jd_base) =
                make_float4(sv[0], sv[1], sv[2], sv[3]);
            *(float4*)&PSM(i_base + r, jd_base + 4) =
                make_float4(sv[4], sv[5], sv[6], sv[7]);
        }
        __syncthreads();                  /* (c) P visible */

        /* ---- O += P V^T : per-thread 4(i) x 8(d), d packed in pairs ---- */
        #pragma unroll 8
        for (int j = 0; j < 64; j++) {
            float p0 = PSM(i_base + 0, j);
            float p1 = PSM(i_base + 1, j);
            float p2 = PSM(i_base + 2, j);
            float p3 = PSM(i_base + 3, j);
            ulonglong2 v01 = *(ulonglong2*)&VT(j, jd_base);
            ulonglong2 v23 = *(ulonglong2*)&VT(j, jd_base + 4);
            unsigned long long vv[4] = {v01.x, v01.y, v23.x, v23.y};
            unsigned long long pp0 = pk2(p0, p0), pp1 = pk2(p1, p1);
            unsigned long long pp2 = pk2(p2, p2), pp3 = pk2(p3, p3);
            #pragma unroll
            for (int c = 0; c < 4; c++) {
                o2[0][c] = ffma2(pp0, vv[c], o2[0][c]);
                o2[1][c] = ffma2(pp1, vv[c], o2[1][c]);
                o2[2][c] = ffma2(pp2, vv[c], o2[2][c]);
                o2[3][c] = ffma2(pp3, vv[c], o2[3][c]);
            }
        }
        __syncthreads();                  /* (d) before overwriting tiles */
    }

    /* ---- epilogue: ao[b, h*64+d, i0+i] = O[i][d] / l[i] ---- */
    float ov[4][8];
    #pragma unroll
    for (int r = 0; r < 4; r++) {
        float invl = 1.f / l_i[r];
        #pragma unroll
        for (int c = 0; c < 4; c++) {
            float lo, hi;
            upk2(o2[r][c], lo, hi);
            ov[r][2 * c] = lo * invl; ov[r][2 * c + 1] = hi * invl;
        }
    }
    float* aop = ao + (long)b * HIDDEN * NPOS + (long)h * DIM_HEAD * NPOS
               + i0 + i_base;
    #pragma unroll
    for (int dd = 0; dd < 8; dd++) {
        float4 v = make_float4(ov[0][dd], ov[1][dd], ov[2][dd], ov[3][dd]);
        *(float4*)(aop + (long)(jd_base + dd) * NPOS) = v;
    }
}

/* ===================================================================== */
extern "C" void kernel_launch(void* const* d_in, const int* in_sizes, int n_in,
                              void* d_out, int out_size) {
    const float* x    = (const float*)d_in[0];
    const float* g    = (const float*)d_in[1];
    const float* Wqkv = (const float*)d_in[2];
    const float* Wout = (const float*)d_in[3];
    const float* bout = (const float*)d_in[4];
    float* out = (float*)d_out;

    float *xn, *qkv, *ao;
    cudaGetSymbolAddress((void**)&xn,  g_xn);
    cudaGetSymbolAddress((void**)&qkv, g_qkv);
    cudaGetSymbolAddress((void**)&ao,  g_ao);

    /* 1. LayerNorm */
    ln_kernel<<<(BATCH * NPOS) / 64, 256>>>(x, g, xn);

    /* 2. QKV projection */
    gemm_wx<<<dim3(QKV_ROWS / 128, NPOS / 64, BATCH), 256>>>(
        Wqkv, xn, qkv, nullptr, QKV_ROWS, CDIM);

    /* 3. attention */
    size_t smem = 25344 * sizeof(float);   /* 101376 B */
    cudaFuncSetAttribute(attn_kernel,
                         cudaFuncAttributeMaxDynamicSharedMemorySize,
                         (int)smem);
    attn_kernel<<<dim3(NPOS / 128, BATCH * HEADS), 256, smem>>>(qkv, ao);

    /* 4. output projection + bias */
    gemm_wx<<<dim3(HIDDEN / 128, NPOS / 64, BATCH), 256>>>(
        Wout, ao, out, bout, HIDDEN, CDIM);
}